// round 5
// baseline (speedup 1.0000x reference)
#include <cuda_runtime.h>
#include <math.h>

#define B_   16
#define H_   128
#define W_   128
#define C_   256
#define CA_  128
#define NTOK 256
#define TOT_TOK (B_*NTOK)

__device__ float g_xs[TOT_TOK * C_];
__device__ float g_q [TOT_TOK * CA_];
__device__ float g_k [TOT_TOK * CA_];
__device__ float g_v [TOT_TOK * CA_];
__device__ float g_ow[TOT_TOK * C_];

// ---- packed fp32x2 helpers (Blackwell) ------------------------------------
__device__ __forceinline__ unsigned long long fma2(unsigned long long a,
                                                   unsigned long long b,
                                                   unsigned long long c) {
    unsigned long long d;
    asm("fma.rn.f32x2 %0, %1, %2, %3;" : "=l"(d) : "l"(a), "l"(b), "l"(c));
    return d;
}
__device__ __forceinline__ unsigned long long dup2(float x) {
    unsigned long long r;
    asm("mov.b64 %0, {%1, %1};" : "=l"(r) : "f"(x));
    return r;
}
__device__ __forceinline__ float2 upk(unsigned long long v) {
    float2 f;
    asm("mov.b64 {%0, %1}, %2;" : "=f"(f.x), "=f"(f.y) : "l"(v));
    return f;
}

// ---------------------------------------------------------------------------
// Kernel 1: bilinear downsample 128x128 -> 16x16 (half the tokens per call)
// ---------------------------------------------------------------------------
__global__ void k_down(const float* __restrict__ x, int tok0) {
    int token = tok0 + blockIdx.x;
    int b = token >> 8;
    int ij = token & 255;
    int i = ij >> 4, j = ij & 15;
    int c = threadIdx.x;
    const float* base = x + ((((size_t)b * H_ + (8*i+3)) * W_) + (8*j+3)) * C_;
    float v = base[c] + base[C_ + c] + base[W_*C_ + c] + base[W_*C_ + C_ + c];
    g_xs[(size_t)token * C_ + c] = 0.25f * v;
}

// ---------------------------------------------------------------------------
// Kernel 2: QKV projections, half the rows per call (row0 offset)
// ---------------------------------------------------------------------------
__global__ void k_qkv(const float* __restrict__ Wq,
                      const float* __restrict__ Wk,
                      const float* __restrict__ Wv, int row0) {
    int bm = blockIdx.x, bn = blockIdx.y;
    int wi = bn >> 1;
    int coloff = (bn & 1) * 64;
    const float* Bmat = (wi == 0 ? Wq : (wi == 1 ? Wk : Wv));
    float* Cout = (wi == 0 ? g_q : (wi == 1 ? g_k : g_v));

    int r0 = row0 + bm * 64;
    const float* A = g_xs + (size_t)r0 * C_;

    __shared__ float As[16][68];
    __shared__ float Bs[16][64];

    int tid = threadIdx.x;
    int tx = tid & 15, ty = tid >> 4;
    int arow = tid >> 2, ak = (tid & 3) * 4;
    int brow = tid >> 4, bcol = (tid & 15) * 4;

    float acc[4][4] = {};

    for (int k0 = 0; k0 < C_; k0 += 16) {
        float4 av = *(const float4*)(A + (size_t)arow * C_ + k0 + ak);
        As[ak+0][arow] = av.x; As[ak+1][arow] = av.y;
        As[ak+2][arow] = av.z; As[ak+3][arow] = av.w;
        float4 bv = *(const float4*)(Bmat + (size_t)(k0 + brow) * CA_ + coloff + bcol);
        *(float4*)&Bs[brow][bcol] = bv;
        __syncthreads();
#pragma unroll
        for (int kk = 0; kk < 16; ++kk) {
            float4 b4 = *(const float4*)&Bs[kk][tx*4];
            float a0 = As[kk][ty*4+0], a1 = As[kk][ty*4+1];
            float a2 = As[kk][ty*4+2], a3 = As[kk][ty*4+3];
            acc[0][0] += a0*b4.x; acc[0][1] += a0*b4.y; acc[0][2] += a0*b4.z; acc[0][3] += a0*b4.w;
            acc[1][0] += a1*b4.x; acc[1][1] += a1*b4.y; acc[1][2] += a1*b4.z; acc[1][3] += a1*b4.w;
            acc[2][0] += a2*b4.x; acc[2][1] += a2*b4.y; acc[2][2] += a2*b4.z; acc[2][3] += a2*b4.w;
            acc[3][0] += a3*b4.x; acc[3][1] += a3*b4.y; acc[3][2] += a3*b4.z; acc[3][3] += a3*b4.w;
        }
        __syncthreads();
    }
#pragma unroll
    for (int i = 0; i < 4; ++i) {
        float4 r = make_float4(acc[i][0], acc[i][1], acc[i][2], acc[i][3]);
        *(float4*)&Cout[(size_t)(r0 + ty*4 + i) * CA_ + coloff + tx*4] = r;
    }
}

// ---------------------------------------------------------------------------
// Kernel 3: fused attention + output projection + multiplier.
// Block = (batch, 32-query tile), 256 threads.
// smem: Qs[32][132] (later reused as O) | KV[128][132] (K, V, then Wo chunks)
//       | S[32][264] | MS[256] (precomputed channel multiplier)
// ---------------------------------------------------------------------------
#define QP 132
#define SP 264
#define ATTN_SMEM ((32*QP + 128*QP + 32*SP + 256) * 4)

__global__ void k_attn(const float* __restrict__ Wo,
                       const float* __restrict__ gw, int blk0) {
    extern __shared__ float smem[];
    float* Qs = smem;                       // 32*132
    float* KV = smem + 32*QP;               // 128*132
    float* S  = smem + 32*QP + 128*QP;      // 32*264
    float* MS = S + 32*SP;                  // 256

    int blk = blk0 + blockIdx.x;
    int b  = blk >> 3;
    int qt = blk & 7;
    const float* qg = g_q + (size_t)(b * NTOK + qt * 32) * CA_;
    const float* kg = g_k + (size_t)b * NTOK * CA_;
    const float* vg = g_v + (size_t)b * NTOK * CA_;

    int tid = threadIdx.x;
    int qy = tid >> 5;       // 0..7 -> query rows qy*4..qy*4+3
    int kx = tid & 31;       // key lane / col lane

    // channel multiplier (once)
    MS[tid] = 0.5f * tanhf(4.0f * gw[tid] + 2.5f);

    // load Q tile
    for (int i = tid; i < 32 * 32; i += 256) {
        int r = i >> 5, c = (i & 31) * 4;
        *(float4*)&Qs[r*QP + c] = *(const float4*)(qg + r*CA_ + c);
    }

    // ---- scores: two chunks of 128 keys ----
    for (int ch = 0; ch < 2; ++ch) {
        __syncthreads();
        const float* ksrc = kg + (size_t)ch * 128 * CA_;
        for (int i = tid; i < 128 * 32; i += 256) {
            int r = i >> 5, c = (i & 31) * 4;
            *(float4*)&KV[r*QP + c] = *(const float4*)(ksrc + r*CA_ + c);
        }
        __syncthreads();

        unsigned long long acc2[4][4];
#pragma unroll
        for (int i = 0; i < 4; ++i)
#pragma unroll
            for (int m = 0; m < 4; ++m) acc2[i][m] = 0ULL;

#pragma unroll 2
        for (int d4 = 0; d4 < 32; ++d4) {
            int dof = d4 * 4;
            ulonglong2 q0 = *(const ulonglong2*)&Qs[(qy*4+0)*QP + dof];
            ulonglong2 q1 = *(const ulonglong2*)&Qs[(qy*4+1)*QP + dof];
            ulonglong2 q2 = *(const ulonglong2*)&Qs[(qy*4+2)*QP + dof];
            ulonglong2 q3 = *(const ulonglong2*)&Qs[(qy*4+3)*QP + dof];
            ulonglong2 k0 = *(const ulonglong2*)&KV[(kx     )*QP + dof];
            ulonglong2 k1 = *(const ulonglong2*)&KV[(kx + 32)*QP + dof];
            ulonglong2 k2 = *(const ulonglong2*)&KV[(kx + 64)*QP + dof];
            ulonglong2 k3 = *(const ulonglong2*)&KV[(kx + 96)*QP + dof];
#define SC(i, qv)                                            \
            acc2[i][0] = fma2(qv.x, k0.x, acc2[i][0]);       \
            acc2[i][0] = fma2(qv.y, k0.y, acc2[i][0]);       \
            acc2[i][1] = fma2(qv.x, k1.x, acc2[i][1]);       \
            acc2[i][1] = fma2(qv.y, k1.y, acc2[i][1]);       \
            acc2[i][2] = fma2(qv.x, k2.x, acc2[i][2]);       \
            acc2[i][2] = fma2(qv.y, k2.y, acc2[i][2]);       \
            acc2[i][3] = fma2(qv.x, k3.x, acc2[i][3]);       \
            acc2[i][3] = fma2(qv.y, k3.y, acc2[i][3]);
            SC(0, q0) SC(1, q1) SC(2, q2) SC(3, q3)
#undef SC
        }
#pragma unroll
        for (int i = 0; i < 4; ++i)
#pragma unroll
            for (int m = 0; m < 4; ++m) {
                float2 p = upk(acc2[i][m]);
                S[(qy*4+i)*SP + ch*128 + kx + 32*m] = p.x + p.y;
            }
    }
    __syncthreads();

    // ---- softmax over 256 keys per query row ----
    {
        int row = tid >> 3, sub = tid & 7;
        float* srow = &S[row * SP];
        float m = -1e30f;
#pragma unroll
        for (int i = 0; i < 32; ++i) m = fmaxf(m, srow[sub + 8*i]);
        m = fmaxf(m, __shfl_xor_sync(0xffffffffu, m, 4, 8));
        m = fmaxf(m, __shfl_xor_sync(0xffffffffu, m, 2, 8));
        m = fmaxf(m, __shfl_xor_sync(0xffffffffu, m, 1, 8));
        float sum = 0.f;
#pragma unroll
        for (int i = 0; i < 32; ++i) {
            float e = __expf(srow[sub + 8*i] - m);
            srow[sub + 8*i] = e;
            sum += e;
        }
        sum += __shfl_xor_sync(0xffffffffu, sum, 4, 8);
        sum += __shfl_xor_sync(0xffffffffu, sum, 2, 8);
        sum += __shfl_xor_sync(0xffffffffu, sum, 1, 8);
        float inv = 1.0f / sum;
#pragma unroll
        for (int i = 0; i < 32; ++i) srow[sub + 8*i] *= inv;
    }

    // ---- O = P @ V ----
    int dx = tid & 31;
    unsigned long long po[4][2];
#pragma unroll
    for (int i = 0; i < 4; ++i) { po[i][0] = 0ULL; po[i][1] = 0ULL; }

    for (int ch = 0; ch < 2; ++ch) {
        __syncthreads();
        const float* vsrc = vg + (size_t)ch * 128 * CA_;
        for (int i = tid; i < 128 * 32; i += 256) {
            int r = i >> 5, c = (i & 31) * 4;
            *(float4*)&KV[r*QP + c] = *(const float4*)(vsrc + r*CA_ + c);
        }
        __syncthreads();

#pragma unroll 4
        for (int kk = 0; kk < 128; ++kk) {
            ulonglong2 vv = *(const ulonglong2*)&KV[kk*QP + dx*4];
#pragma unroll
            for (int i = 0; i < 4; ++i) {
                unsigned long long pd = dup2(S[(qy*4+i)*SP + ch*128 + kk]);
                po[i][0] = fma2(pd, vv.x, po[i][0]);
                po[i][1] = fma2(pd, vv.y, po[i][1]);
            }
        }
    }

    // stash O into Qs (Q no longer needed): Os[row][d], row pitch QP
    __syncthreads();   // all threads done with PV reads before KV reuse below
#pragma unroll
    for (int i = 0; i < 4; ++i) {
        float2 lo = upk(po[i][0]);
        float2 hi = upk(po[i][1]);
        *(float4*)&Qs[(qy*4+i)*QP + dx*4] = make_float4(lo.x, lo.y, hi.x, hi.y);
    }

    // ---- fused output projection: OW = (O @ Wo) * mult, two 128-col chunks
    for (int c2 = 0; c2 < 2; ++c2) {
        __syncthreads();   // Os stores visible; previous KV reads done
        const float* wsrc = Wo + c2 * 128;
        for (int i = tid; i < 128 * 32; i += 256) {
            int r = i >> 5, c = (i & 31) * 4;
            *(float4*)&KV[r*QP + c] = *(const float4*)(wsrc + (size_t)r * C_ + c);
        }
        __syncthreads();

        unsigned long long oa[4][2];
#pragma unroll
        for (int i = 0; i < 4; ++i) { oa[i][0] = 0ULL; oa[i][1] = 0ULL; }

#pragma unroll 4
        for (int k = 0; k < 128; ++k) {
            ulonglong2 wv = *(const ulonglong2*)&KV[k*QP + dx*4];
#pragma unroll
            for (int i = 0; i < 4; ++i) {
                unsigned long long ad = dup2(Qs[(qy*4+i)*QP + k]);
                oa[i][0] = fma2(ad, wv.x, oa[i][0]);
                oa[i][1] = fma2(ad, wv.y, oa[i][1]);
            }
        }

        int col = c2*128 + dx*4;
        float4 mm = *(const float4*)&MS[col];
#pragma unroll
        for (int i = 0; i < 4; ++i) {
            float2 lo = upk(oa[i][0]);
            float2 hi = upk(oa[i][1]);
            size_t row = (size_t)(b*NTOK + qt*32 + qy*4 + i);
            float4 r = make_float4(lo.x*mm.x, lo.y*mm.y, hi.x*mm.z, hi.y*mm.w);
            *(float4*)&g_ow[row*C_ + col] = r;
        }
    }
}

// ---------------------------------------------------------------------------
// Kernel 4: bilinear upsample with 8-pixel horizontal reuse (half rows/call)
// ---------------------------------------------------------------------------
__global__ void k_up(float* __restrict__ out, int bh0) {
    int bx = bh0 + blockIdx.x;
    int h = bx & 127;
    int b = bx >> 7;
    int tid = threadIdx.x;
    int m  = tid >> 6;     // 0..15
    int c4 = tid & 63;     // channel quad

    float yy = h * 0.125f - 0.4375f;
    float y0f = floorf(yy);
    float fy = yy - y0f;
    int y0 = (int)y0f;
    int y1 = y0 + 1;
    y0 = max(y0, 0); y1 = min(y1, 15);

    int cL = max(m - 1, 0);
    int cR = min(m + 1, 15);

    const float* src = g_ow + (size_t)b * NTOK * C_;
    float4 aL = *((const float4*)(src + (size_t)(y0*16 + cL) * C_) + c4);
    float4 aM = *((const float4*)(src + (size_t)(y0*16 + m ) * C_) + c4);
    float4 aR = *((const float4*)(src + (size_t)(y0*16 + cR) * C_) + c4);
    float4 bL = *((const float4*)(src + (size_t)(y1*16 + cL) * C_) + c4);
    float4 bM = *((const float4*)(src + (size_t)(y1*16 + m ) * C_) + c4);
    float4 bR = *((const float4*)(src + (size_t)(y1*16 + cR) * C_) + c4);

    float w0 = 1.f - fy;
    float4 vL, vM, vR;
    vL.x = w0*aL.x + fy*bL.x; vL.y = w0*aL.y + fy*bL.y; vL.z = w0*aL.z + fy*bL.z; vL.w = w0*aL.w + fy*bL.w;
    vM.x = w0*aM.x + fy*bM.x; vM.y = w0*aM.y + fy*bM.y; vM.z = w0*aM.z + fy*bM.z; vM.w = w0*aM.w + fy*bM.w;
    vR.x = w0*aR.x + fy*bR.x; vR.y = w0*aR.y + fy*bR.y; vR.z = w0*aR.z + fy*bR.z; vR.w = w0*aR.w + fy*bR.w;

    float4* obase = (float4*)out + ((size_t)(b*H_ + h) * W_ + m*8) * (C_/4) + c4;
#pragma unroll
    for (int t = 0; t < 8; ++t) {
        float fx;
        float4 p, q, r;
        if (t < 4) { fx = 0.5625f + t * 0.125f; p = vL; q = vM; }
        else       { fx = t * 0.125f - 0.4375f; p = vM; q = vR; }
        float ax = 1.f - fx;
        r.x = ax*p.x + fx*q.x;
        r.y = ax*p.y + fx*q.y;
        r.z = ax*p.z + fx*q.z;
        r.w = ax*p.w + fx*q.w;
        obase[(size_t)t * (C_/4)] = r;
    }
}

// ---------------------------------------------------------------------------
extern "C" void kernel_launch(void* const* d_in, const int* in_sizes, int n_in,
                              void* d_out, int out_size) {
    const float* x  = (const float*)d_in[0];
    const float* Wq = (const float*)d_in[1];
    const float* Wk = (const float*)d_in[2];
    const float* Wv = (const float*)d_in[3];
    const float* Wo = (const float*)d_in[4];
    const float* gw = (const float*)d_in[5];
    float* out = (float*)d_out;

    static cudaStream_t s1 = nullptr, s2 = nullptr;
    static cudaEvent_t ef = nullptr, e1 = nullptr, e2 = nullptr;
    if (!s1) {
        cudaFuncSetAttribute(k_attn, cudaFuncAttributeMaxDynamicSharedMemorySize, ATTN_SMEM);
        cudaStreamCreateWithFlags(&s1, cudaStreamNonBlocking);
        cudaStreamCreateWithFlags(&s2, cudaStreamNonBlocking);
        cudaEventCreateWithFlags(&ef, cudaEventDisableTiming);
        cudaEventCreateWithFlags(&e1, cudaEventDisableTiming);
        cudaEventCreateWithFlags(&e2, cudaEventDisableTiming);
    }

    // fork
    cudaEventRecord(ef, 0);
    cudaStreamWaitEvent(s1, ef, 0);
    cudaStreamWaitEvent(s2, ef, 0);

    cudaStream_t ss[2] = {s1, s2};
    for (int h = 0; h < 2; ++h) {
        cudaStream_t s = ss[h];
        k_down<<<TOT_TOK/2, 256, 0, s>>>(x, h * (TOT_TOK/2));
        k_qkv<<<dim3(32, 6), 256, 0, s>>>(Wq, Wk, Wv, h * (TOT_TOK/2));
        k_attn<<<64, 256, ATTN_SMEM, s>>>(Wo, gw, h * 64);
        k_up<<<B_*H_/2, 1024, 0, s>>>(out, h * (B_*H_/2));
    }

    // join
    cudaEventRecord(e1, s1);
    cudaEventRecord(e2, s2);
    cudaStreamWaitEvent(0, e1, 0);
    cudaStreamWaitEvent(0, e2, 0);
}

// round 6
// speedup vs baseline: 1.1388x; 1.1388x over previous
#include <cuda_runtime.h>
#include <math.h>

#define B_   16
#define H_   128
#define W_   128
#define C_   256
#define CA_  128
#define NTOK 256
#define TOT_TOK (B_*NTOK)

__device__ float g_xs[TOT_TOK * C_];
__device__ float g_q [TOT_TOK * CA_];
__device__ float g_k [TOT_TOK * CA_];
__device__ float g_v [TOT_TOK * CA_];
__device__ float g_ow[TOT_TOK * C_];

// ---- packed fp32x2 helpers (Blackwell) ------------------------------------
__device__ __forceinline__ unsigned long long fma2(unsigned long long a,
                                                   unsigned long long b,
                                                   unsigned long long c) {
    unsigned long long d;
    asm("fma.rn.f32x2 %0, %1, %2, %3;" : "=l"(d) : "l"(a), "l"(b), "l"(c));
    return d;
}
__device__ __forceinline__ unsigned long long dup2(float x) {
    unsigned long long r;
    asm("mov.b64 %0, {%1, %1};" : "=l"(r) : "f"(x));
    return r;
}
__device__ __forceinline__ float2 upk(unsigned long long v) {
    float2 f;
    asm("mov.b64 {%0, %1}, %2;" : "=f"(f.x), "=f"(f.y) : "l"(v));
    return f;
}

// ---------------------------------------------------------------------------
// Kernel 1: bilinear downsample 128x128 -> 16x16
// ---------------------------------------------------------------------------
__global__ void k_down(const float* __restrict__ x) {
    int token = blockIdx.x;
    int b = token >> 8;
    int ij = token & 255;
    int i = ij >> 4, j = ij & 15;
    int c = threadIdx.x;
    const float* base = x + ((((size_t)b * H_ + (8*i+3)) * W_) + (8*j+3)) * C_;
    float v = base[c] + base[C_ + c] + base[W_*C_ + c] + base[W_*C_ + C_ + c];
    g_xs[(size_t)token * C_ + c] = 0.25f * v;
}

// ---------------------------------------------------------------------------
// Kernel 2: QKV projections, f32x2 inner loop.
// grid (64, 6): y -> {Wq,Wk,Wv} x column halves
// ---------------------------------------------------------------------------
__global__ void k_qkv(const float* __restrict__ Wq,
                      const float* __restrict__ Wk,
                      const float* __restrict__ Wv) {
    int bm = blockIdx.x, bn = blockIdx.y;
    int wi = bn >> 1;
    int coloff = (bn & 1) * 64;
    const float* Bmat = (wi == 0 ? Wq : (wi == 1 ? Wk : Wv));
    float* Cout = (wi == 0 ? g_q : (wi == 1 ? g_k : g_v));

    const float* A = g_xs + (size_t)bm * 64 * C_;

    __shared__ float As[16][68];
    __shared__ float Bs[16][64];

    int tid = threadIdx.x;
    int tx = tid & 15, ty = tid >> 4;
    int arow = tid >> 2, ak = (tid & 3) * 4;
    int brow = tid >> 4, bcol = (tid & 15) * 4;

    unsigned long long acc2[4][2];
#pragma unroll
    for (int i = 0; i < 4; ++i) { acc2[i][0] = 0ULL; acc2[i][1] = 0ULL; }

    for (int k0 = 0; k0 < C_; k0 += 16) {
        float4 av = *(const float4*)(A + (size_t)arow * C_ + k0 + ak);
        As[ak+0][arow] = av.x; As[ak+1][arow] = av.y;
        As[ak+2][arow] = av.z; As[ak+3][arow] = av.w;
        float4 bv = *(const float4*)(Bmat + (size_t)(k0 + brow) * CA_ + coloff + bcol);
        *(float4*)&Bs[brow][bcol] = bv;
        __syncthreads();
#pragma unroll
        for (int kk = 0; kk < 16; ++kk) {
            ulonglong2 bu = *(const ulonglong2*)&Bs[kk][tx*4];
            unsigned long long a0 = dup2(As[kk][ty*4+0]);
            unsigned long long a1 = dup2(As[kk][ty*4+1]);
            unsigned long long a2 = dup2(As[kk][ty*4+2]);
            unsigned long long a3 = dup2(As[kk][ty*4+3]);
            acc2[0][0] = fma2(a0, bu.x, acc2[0][0]);
            acc2[0][1] = fma2(a0, bu.y, acc2[0][1]);
            acc2[1][0] = fma2(a1, bu.x, acc2[1][0]);
            acc2[1][1] = fma2(a1, bu.y, acc2[1][1]);
            acc2[2][0] = fma2(a2, bu.x, acc2[2][0]);
            acc2[2][1] = fma2(a2, bu.y, acc2[2][1]);
            acc2[3][0] = fma2(a3, bu.x, acc2[3][0]);
            acc2[3][1] = fma2(a3, bu.y, acc2[3][1]);
        }
        __syncthreads();
    }
#pragma unroll
    for (int i = 0; i < 4; ++i) {
        float2 lo = upk(acc2[i][0]);
        float2 hi = upk(acc2[i][1]);
        float4 r = make_float4(lo.x, lo.y, hi.x, hi.y);
        *(float4*)&Cout[(size_t)(bm*64 + ty*4 + i) * CA_ + coloff + tx*4] = r;
    }
}

// ---------------------------------------------------------------------------
// Kernel 3: fused attention + output projection + multiplier.
// Block = (batch, 32-query tile), 256 threads, 128 blocks.
// smem: Qs[32][132] (later reused as O) | KV[128][132] | S[32][264] | MS[256]
// ---------------------------------------------------------------------------
#define QP 132
#define SP 264
#define ATTN_SMEM ((32*QP + 128*QP + 32*SP + 256) * 4)

__global__ void k_attn(const float* __restrict__ Wo,
                       const float* __restrict__ gw) {
    extern __shared__ float smem[];
    float* Qs = smem;                       // 32*132
    float* KV = smem + 32*QP;               // 128*132
    float* S  = smem + 32*QP + 128*QP;      // 32*264
    float* MS = S + 32*SP;                  // 256

    int blk = blockIdx.x;
    int b  = blk >> 3;
    int qt = blk & 7;
    const float* qg = g_q + (size_t)(b * NTOK + qt * 32) * CA_;
    const float* kg = g_k + (size_t)b * NTOK * CA_;
    const float* vg = g_v + (size_t)b * NTOK * CA_;

    int tid = threadIdx.x;
    int qy = tid >> 5;       // 0..7 -> query rows qy*4..qy*4+3
    int kx = tid & 31;

    MS[tid] = 0.5f * tanhf(4.0f * gw[tid] + 2.5f);

    for (int i = tid; i < 32 * 32; i += 256) {
        int r = i >> 5, c = (i & 31) * 4;
        *(float4*)&Qs[r*QP + c] = *(const float4*)(qg + r*CA_ + c);
    }

    // ---- scores: two chunks of 128 keys ----
    for (int ch = 0; ch < 2; ++ch) {
        __syncthreads();
        const float* ksrc = kg + (size_t)ch * 128 * CA_;
        for (int i = tid; i < 128 * 32; i += 256) {
            int r = i >> 5, c = (i & 31) * 4;
            *(float4*)&KV[r*QP + c] = *(const float4*)(ksrc + r*CA_ + c);
        }
        __syncthreads();

        unsigned long long acc2[4][4];
#pragma unroll
        for (int i = 0; i < 4; ++i)
#pragma unroll
            for (int m = 0; m < 4; ++m) acc2[i][m] = 0ULL;

#pragma unroll 2
        for (int d4 = 0; d4 < 32; ++d4) {
            int dof = d4 * 4;
            ulonglong2 q0 = *(const ulonglong2*)&Qs[(qy*4+0)*QP + dof];
            ulonglong2 q1 = *(const ulonglong2*)&Qs[(qy*4+1)*QP + dof];
            ulonglong2 q2 = *(const ulonglong2*)&Qs[(qy*4+2)*QP + dof];
            ulonglong2 q3 = *(const ulonglong2*)&Qs[(qy*4+3)*QP + dof];
            ulonglong2 k0 = *(const ulonglong2*)&KV[(kx     )*QP + dof];
            ulonglong2 k1 = *(const ulonglong2*)&KV[(kx + 32)*QP + dof];
            ulonglong2 k2 = *(const ulonglong2*)&KV[(kx + 64)*QP + dof];
            ulonglong2 k3 = *(const ulonglong2*)&KV[(kx + 96)*QP + dof];
#define SC(i, qv)                                            \
            acc2[i][0] = fma2(qv.x, k0.x, acc2[i][0]);       \
            acc2[i][0] = fma2(qv.y, k0.y, acc2[i][0]);       \
            acc2[i][1] = fma2(qv.x, k1.x, acc2[i][1]);       \
            acc2[i][1] = fma2(qv.y, k1.y, acc2[i][1]);       \
            acc2[i][2] = fma2(qv.x, k2.x, acc2[i][2]);       \
            acc2[i][2] = fma2(qv.y, k2.y, acc2[i][2]);       \
            acc2[i][3] = fma2(qv.x, k3.x, acc2[i][3]);       \
            acc2[i][3] = fma2(qv.y, k3.y, acc2[i][3]);
            SC(0, q0) SC(1, q1) SC(2, q2) SC(3, q3)
#undef SC
        }
#pragma unroll
        for (int i = 0; i < 4; ++i)
#pragma unroll
            for (int m = 0; m < 4; ++m) {
                float2 p = upk(acc2[i][m]);
                S[(qy*4+i)*SP + ch*128 + kx + 32*m] = p.x + p.y;
            }
    }
    __syncthreads();

    // ---- softmax over 256 keys per query row ----
    {
        int row = tid >> 3, sub = tid & 7;
        float* srow = &S[row * SP];
        float m = -1e30f;
#pragma unroll
        for (int i = 0; i < 32; ++i) m = fmaxf(m, srow[sub + 8*i]);
        m = fmaxf(m, __shfl_xor_sync(0xffffffffu, m, 4, 8));
        m = fmaxf(m, __shfl_xor_sync(0xffffffffu, m, 2, 8));
        m = fmaxf(m, __shfl_xor_sync(0xffffffffu, m, 1, 8));
        float sum = 0.f;
#pragma unroll
        for (int i = 0; i < 32; ++i) {
            float e = __expf(srow[sub + 8*i] - m);
            srow[sub + 8*i] = e;
            sum += e;
        }
        sum += __shfl_xor_sync(0xffffffffu, sum, 4, 8);
        sum += __shfl_xor_sync(0xffffffffu, sum, 2, 8);
        sum += __shfl_xor_sync(0xffffffffu, sum, 1, 8);
        float inv = 1.0f / sum;
#pragma unroll
        for (int i = 0; i < 32; ++i) srow[sub + 8*i] *= inv;
    }

    // ---- O = P @ V ----
    int dx = tid & 31;
    unsigned long long po[4][2];
#pragma unroll
    for (int i = 0; i < 4; ++i) { po[i][0] = 0ULL; po[i][1] = 0ULL; }

    for (int ch = 0; ch < 2; ++ch) {
        __syncthreads();
        const float* vsrc = vg + (size_t)ch * 128 * CA_;
        for (int i = tid; i < 128 * 32; i += 256) {
            int r = i >> 5, c = (i & 31) * 4;
            *(float4*)&KV[r*QP + c] = *(const float4*)(vsrc + r*CA_ + c);
        }
        __syncthreads();

#pragma unroll 4
        for (int kk = 0; kk < 128; ++kk) {
            ulonglong2 vv = *(const ulonglong2*)&KV[kk*QP + dx*4];
#pragma unroll
            for (int i = 0; i < 4; ++i) {
                unsigned long long pd = dup2(S[(qy*4+i)*SP + ch*128 + kk]);
                po[i][0] = fma2(pd, vv.x, po[i][0]);
                po[i][1] = fma2(pd, vv.y, po[i][1]);
            }
        }
    }

    // stash O into Qs (Q no longer needed)
    __syncthreads();
#pragma unroll
    for (int i = 0; i < 4; ++i) {
        float2 lo = upk(po[i][0]);
        float2 hi = upk(po[i][1]);
        *(float4*)&Qs[(qy*4+i)*QP + dx*4] = make_float4(lo.x, lo.y, hi.x, hi.y);
    }

    // ---- fused output projection: OW = (O @ Wo) * mult, two 128-col chunks
    for (int c2 = 0; c2 < 2; ++c2) {
        __syncthreads();
        const float* wsrc = Wo + c2 * 128;
        for (int i = tid; i < 128 * 32; i += 256) {
            int r = i >> 5, c = (i & 31) * 4;
            *(float4*)&KV[r*QP + c] = *(const float4*)(wsrc + (size_t)r * C_ + c);
        }
        __syncthreads();

        unsigned long long oa[4][2];
#pragma unroll
        for (int i = 0; i < 4; ++i) { oa[i][0] = 0ULL; oa[i][1] = 0ULL; }

#pragma unroll 4
        for (int k = 0; k < 128; ++k) {
            ulonglong2 wv = *(const ulonglong2*)&KV[k*QP + dx*4];
#pragma unroll
            for (int i = 0; i < 4; ++i) {
                unsigned long long ad = dup2(Qs[(qy*4+i)*QP + k]);
                oa[i][0] = fma2(ad, wv.x, oa[i][0]);
                oa[i][1] = fma2(ad, wv.y, oa[i][1]);
            }
        }

        int col = c2*128 + dx*4;
        float4 mm = *(const float4*)&MS[col];
#pragma unroll
        for (int i = 0; i < 4; ++i) {
            float2 lo = upk(oa[i][0]);
            float2 hi = upk(oa[i][1]);
            size_t row = (size_t)(b*NTOK + qt*32 + qy*4 + i);
            float4 r = make_float4(lo.x*mm.x, lo.y*mm.y, hi.x*mm.z, hi.y*mm.w);
            *(float4*)&g_ow[row*C_ + col] = r;
        }
    }
}

// ---------------------------------------------------------------------------
// Kernel 4: bilinear upsample with 8-pixel horizontal reuse.
// ---------------------------------------------------------------------------
__global__ void k_up(float* __restrict__ out) {
    int bx = blockIdx.x;
    int h = bx & 127;
    int b = bx >> 7;
    int tid = threadIdx.x;
    int m  = tid >> 6;     // 0..15
    int c4 = tid & 63;     // channel quad

    float yy = h * 0.125f - 0.4375f;
    float y0f = floorf(yy);
    float fy = yy - y0f;
    int y0 = (int)y0f;
    int y1 = y0 + 1;
    y0 = max(y0, 0); y1 = min(y1, 15);

    int cL = max(m - 1, 0);
    int cR = min(m + 1, 15);

    const float* src = g_ow + (size_t)b * NTOK * C_;
    float4 aL = *((const float4*)(src + (size_t)(y0*16 + cL) * C_) + c4);
    float4 aM = *((const float4*)(src + (size_t)(y0*16 + m ) * C_) + c4);
    float4 aR = *((const float4*)(src + (size_t)(y0*16 + cR) * C_) + c4);
    float4 bL = *((const float4*)(src + (size_t)(y1*16 + cL) * C_) + c4);
    float4 bM = *((const float4*)(src + (size_t)(y1*16 + m ) * C_) + c4);
    float4 bR = *((const float4*)(src + (size_t)(y1*16 + cR) * C_) + c4);

    float w0 = 1.f - fy;
    float4 vL, vM, vR;
    vL.x = w0*aL.x + fy*bL.x; vL.y = w0*aL.y + fy*bL.y; vL.z = w0*aL.z + fy*bL.z; vL.w = w0*aL.w + fy*bL.w;
    vM.x = w0*aM.x + fy*bM.x; vM.y = w0*aM.y + fy*bM.y; vM.z = w0*aM.z + fy*bM.z; vM.w = w0*aM.w + fy*bM.w;
    vR.x = w0*aR.x + fy*bR.x; vR.y = w0*aR.y + fy*bR.y; vR.z = w0*aR.z + fy*bR.z; vR.w = w0*aR.w + fy*bR.w;

    float4* obase = (float4*)out + ((size_t)(b*H_ + h) * W_ + m*8) * (C_/4) + c4;
#pragma unroll
    for (int t = 0; t < 8; ++t) {
        float fx;
        float4 p, q, r;
        if (t < 4) { fx = 0.5625f + t * 0.125f; p = vL; q = vM; }
        else       { fx = t * 0.125f - 0.4375f; p = vM; q = vR; }
        float ax = 1.f - fx;
        r.x = ax*p.x + fx*q.x;
        r.y = ax*p.y + fx*q.y;
        r.z = ax*p.z + fx*q.z;
        r.w = ax*p.w + fx*q.w;
        obase[(size_t)t * (C_/4)] = r;
    }
}

// ---------------------------------------------------------------------------
extern "C" void kernel_launch(void* const* d_in, const int* in_sizes, int n_in,
                              void* d_out, int out_size) {
    const float* x  = (const float*)d_in[0];
    const float* Wq = (const float*)d_in[1];
    const float* Wk = (const float*)d_in[2];
    const float* Wv = (const float*)d_in[3];
    const float* Wo = (const float*)d_in[4];
    const float* gw = (const float*)d_in[5];
    float* out = (float*)d_out;

    static bool attr_set = false;
    if (!attr_set) {
        cudaFuncSetAttribute(k_attn, cudaFuncAttributeMaxDynamicSharedMemorySize, ATTN_SMEM);
        attr_set = true;
    }

    k_down<<<TOT_TOK, 256>>>(x);
    k_qkv<<<dim3(64, 6), 256>>>(Wq, Wk, Wv);
    k_attn<<<128, 256, ATTN_SMEM>>>(Wo, gw);
    k_up<<<B_*H_, 1024>>>(out);
}